// round 2
// baseline (speedup 1.0000x reference)
#include <cuda_runtime.h>

// Problem constants (fixed by the dataset)
#define Nn   50000
#define Ee   800000
#define Gg   512
#define DINc 128

typedef unsigned long long ull;

// ---------- f32x2 packed-FMA helpers (sm_103a) ----------
__device__ __forceinline__ ull fma2(ull a, ull b, ull c) {
    ull d;
    asm("fma.rn.f32x2 %0, %1, %2, %3;" : "=l"(d) : "l"(a), "l"(b), "l"(c));
    return d;
}
__device__ __forceinline__ ull pack2(float x, float y) {
    ull r;
    asm("mov.b64 %0, {%1,%2};" : "=l"(r) : "f"(x), "f"(y));
    return r;
}
__device__ __forceinline__ float2 unpack2(ull v) {
    float2 r;
    asm("mov.b64 {%0,%1}, %2;" : "=f"(r.x), "=f"(r.y) : "l"(v));
    return r;
}
__device__ __forceinline__ float sigmoidf_fast(float x) {
    return __fdividef(1.0f, 1.0f + __expf(-x));
}

// Per-layer edge weight matrix in constant memory -> warp-uniform LDCU.64 reads.
__constant__ float cWc[64 * 64];

// ---------- scratch (static device globals) ----------
__device__ float  g_h [(size_t)Nn * 64];
__device__ float  g_e [(size_t)Ee * 64];   // edge residual state
__device__ float  g_z [(size_t)Ee * 64];   // z = e_new * edge_norm
__device__ float  g_Ah[(size_t)Nn * 64];
__device__ float  g_Bh[(size_t)Nn * 64];
__device__ float  g_Dh[(size_t)Nn * 64];
__device__ float  g_Eh[(size_t)Nn * 64];
__device__ float  g_num[(size_t)Nn * 64];
__device__ float  g_den[(size_t)Nn * 64];
__device__ float  g_hn[(size_t)Nn * 64];
__device__ double g_statsP[32][256];       // striped: [0:64) e_sum [64:128) e_sq [128:192) h_sum [192:256) h_sq
__device__ float  g_bnp[256];              // [0:64) mu_e [64:128) inv_e [128:192) mu_h [192:256) inv_h
__device__ float  g_cnt[Gg];

// ---------- initial node embedding: h = nodes_feat @ W_h + b_h ----------
__global__ void __launch_bounds__(256) k_embed_h(const float* __restrict__ x,
                                                 const float* __restrict__ W,
                                                 const float* __restrict__ b) {
    __shared__ __align__(16) float sW[DINc][64];
    __shared__ __align__(16) float sx[16][DINc];
    const int t = threadIdx.x;
    for (int i = t; i < DINc * 64 / 4; i += 256)
        ((float4*)&sW[0][0])[i] = ((const float4*)W)[i];

    const int cq = t & 15, m = t >> 4;
    const float4 bias = ((const float4*)b)[cq];
    const int base = blockIdx.x * 64;

    for (int it = 0; it < 4; it++) {
        const int n0 = base + it * 16;
        __syncthreads();
        for (int i = t; i < 16 * DINc / 4; i += 256) {
            const int row = i >> 5, c4 = i & 31;
            const int n = n0 + row;
            float4 v = make_float4(0.f, 0.f, 0.f, 0.f);
            if (n < Nn) v = ((const float4*)x)[(size_t)n * 32 + c4];
            ((float4*)&sx[row][0])[c4] = v;
        }
        __syncthreads();
        float4 acc = bias;
        #pragma unroll 8
        for (int k = 0; k < DINc; k++) {
            const float xv = sx[m][k];
            const float4 w = ((const float4*)&sW[k][0])[cq];
            acc.x += xv * w.x; acc.y += xv * w.y;
            acc.z += xv * w.z; acc.w += xv * w.w;
        }
        const int n = n0 + m;
        if (n < Nn) ((float4*)g_h)[(size_t)n * 16 + cq] = acc;
    }
}

// ---------- per-layer node GEMMs (Ah,Bh,Dh,Eh), fused node BN+residual of prev layer ----------
extern __shared__ float dsm[];
template<int FUSE>
__global__ void __launch_bounds__(256) k_node_gemm(
        const float* __restrict__ Wa, const float* __restrict__ Wb,
        const float* __restrict__ Wd, const float* __restrict__ We_,
        const float* __restrict__ ba_, const float* __restrict__ bb_,
        const float* __restrict__ bd_, const float* __restrict__ be_,
        const float* __restrict__ gamH, const float* __restrict__ betH) {
    float* sW = dsm;              // 4 * 4096 floats
    float* sx = dsm + 4 * 4096;   // 16 * 64 floats
    const int t = threadIdx.x;

    // block 0 zeroes the striped BN stats accumulators for this layer
    if (blockIdx.x == 0) {
        double* p = &g_statsP[0][0];
        for (int i = t; i < 32 * 256; i += 256) p[i] = 0.0;
    }

    for (int i = t; i < 1024; i += 256) ((float4*)(sW + 0 * 4096))[i] = ((const float4*)Wa)[i];
    for (int i = t; i < 1024; i += 256) ((float4*)(sW + 1 * 4096))[i] = ((const float4*)Wb)[i];
    for (int i = t; i < 1024; i += 256) ((float4*)(sW + 2 * 4096))[i] = ((const float4*)Wd)[i];
    for (int i = t; i < 1024; i += 256) ((float4*)(sW + 3 * 4096))[i] = ((const float4*)We_)[i];

    const int cq = t & 15, m = t >> 4;
    const float4 bA = ((const float4*)ba_)[cq];
    const float4 bB = ((const float4*)bb_)[cq];
    const float4 bD = ((const float4*)bd_)[cq];
    const float4 bE = ((const float4*)be_)[cq];
    const int base = blockIdx.x * 64;

    for (int it = 0; it < 4; it++) {
        const int n0 = base + it * 16;
        __syncthreads();
        {
            const int row = t >> 4, c4 = t & 15;
            const int n = n0 + row;
            float4 v = make_float4(0.f, 0.f, 0.f, 0.f);
            if (n < Nn) {
                const size_t o = (size_t)n * 16 + c4;
                v = ((const float4*)g_h)[o];
                if (FUSE) {
                    const float4 hn = ((const float4*)g_hn)[o];
                    const float4 g4 = ((const float4*)gamH)[c4];
                    const float4 b4 = ((const float4*)betH)[c4];
                    const float4 mu = ((const float4*)(g_bnp + 128))[c4];
                    const float4 iv = ((const float4*)(g_bnp + 192))[c4];
                    v.x += fmaxf(0.f, g4.x * (hn.x - mu.x) * iv.x + b4.x);
                    v.y += fmaxf(0.f, g4.y * (hn.y - mu.y) * iv.y + b4.y);
                    v.z += fmaxf(0.f, g4.z * (hn.z - mu.z) * iv.z + b4.z);
                    v.w += fmaxf(0.f, g4.w * (hn.w - mu.w) * iv.w + b4.w);
                    ((float4*)g_h)[o] = v;   // persist residual-updated h
                }
            }
            ((float4*)sx)[row * 16 + c4] = v;
        }
        __syncthreads();
        float4 aA = bA, aB = bB, aD = bD, aE = bE;
        #pragma unroll 4
        for (int k = 0; k < 64; k++) {
            const float xv = sx[m * 64 + k];
            const float4 wA = ((const float4*)(sW + 0 * 4096 + k * 64))[cq];
            const float4 wB = ((const float4*)(sW + 1 * 4096 + k * 64))[cq];
            const float4 wD = ((const float4*)(sW + 2 * 4096 + k * 64))[cq];
            const float4 wE = ((const float4*)(sW + 3 * 4096 + k * 64))[cq];
            aA.x += xv * wA.x; aA.y += xv * wA.y; aA.z += xv * wA.z; aA.w += xv * wA.w;
            aB.x += xv * wB.x; aB.y += xv * wB.y; aB.z += xv * wB.z; aB.w += xv * wB.w;
            aD.x += xv * wD.x; aD.y += xv * wD.y; aD.z += xv * wD.z; aD.w += xv * wD.w;
            aE.x += xv * wE.x; aE.y += xv * wE.y; aE.z += xv * wE.z; aE.w += xv * wE.w;
        }
        const int n = n0 + m;
        if (n < Nn) {
            const size_t o = (size_t)n * 16 + cq;
            ((float4*)g_Ah)[o] = aA;
            ((float4*)g_Bh)[o] = aB;
            ((float4*)g_Dh)[o] = aD;
            ((float4*)g_Eh)[o] = aE;
            ((float4*)g_num)[o] = make_float4(0.f, 0.f, 0.f, 0.f);
            ((float4*)g_den)[o] = make_float4(0.f, 0.f, 0.f, 0.f);
        }
    }
}

// ---------- fused edge mega-kernel ----------
// MODE 0: first layer  — e from edges_feat embed (writes g_e), writes z, stats
// MODE 1: mid layers   — e = g_e + relu(BN(g_z)) (writes g_e), writes z, stats
// MODE 2: last layer   — e computed on the fly, NO g_e/z/stats writes
template<int MODE>
__global__ void __launch_bounds__(128) k_edge_A(
        const float* __restrict__ bc_,
        const int* __restrict__ src, const int* __restrict__ dst,
        const float* __restrict__ enorm,
        const float* __restrict__ ef, const float* __restrict__ We_,
        const float* __restrict__ be_,
        const float* __restrict__ gamE, const float* __restrict__ betE) {
    __shared__ float sE[64][129];   // row = channel, col = edge-in-block (conflict-free both ways)
    const int tid = threadIdx.x;
    const int edge = blockIdx.x * 128 + tid;
    const int s = src[edge], d = dst[edge];

    float4* ge4 = ((float4*)g_e) + (size_t)edge * 16;

    if (MODE == 0) {
        const float f = ef[edge];
        #pragma unroll
        for (int q = 0; q < 16; q++) {
            const float4 w = ((const float4*)We_)[q];
            const float4 b = ((const float4*)be_)[q];
            const float4 ei = make_float4(fmaf(f, w.x, b.x), fmaf(f, w.y, b.y),
                                          fmaf(f, w.z, b.z), fmaf(f, w.w, b.w));
            ge4[q] = ei;
            sE[4 * q + 0][tid] = ei.x; sE[4 * q + 1][tid] = ei.y;
            sE[4 * q + 2][tid] = ei.z; sE[4 * q + 3][tid] = ei.w;
        }
    } else {
        const float4* gz4c = ((const float4*)g_z) + (size_t)edge * 16;
        #pragma unroll
        for (int q = 0; q < 16; q++) {
            float4 ev = ge4[q];
            const float4 zv = gz4c[q];
            const float4 g4 = ((const float4*)gamE)[q];
            const float4 b4 = ((const float4*)betE)[q];
            const float4 mu = ((const float4*)(g_bnp + 0))[q];
            const float4 iv = ((const float4*)(g_bnp + 64))[q];
            ev.x += fmaxf(0.f, g4.x * (zv.x - mu.x) * iv.x + b4.x);
            ev.y += fmaxf(0.f, g4.y * (zv.y - mu.y) * iv.y + b4.y);
            ev.z += fmaxf(0.f, g4.z * (zv.z - mu.z) * iv.z + b4.z);
            ev.w += fmaxf(0.f, g4.w * (zv.w - mu.w) * iv.w + b4.w);
            if (MODE == 1) ge4[q] = ev;
            sE[4 * q + 0][tid] = ev.x; sE[4 * q + 1][tid] = ev.y;
            sE[4 * q + 2][tid] = ev.z; sE[4 * q + 3][tid] = ev.w;
        }
    }
    __syncthreads();

    // acc = bc + Dh[src] + Eh[dst]
    ull acc[32];
    {
        const float4* D4 = ((const float4*)g_Dh) + (size_t)s * 16;
        const float4* E4 = ((const float4*)g_Eh) + (size_t)d * 16;
        #pragma unroll
        for (int q = 0; q < 16; q++) {
            const float4 bv = ((const float4*)bc_)[q];
            const float4 dv = D4[q];
            const float4 ev = E4[q];
            acc[2 * q]     = pack2(bv.x + dv.x + ev.x, bv.y + dv.y + ev.y);
            acc[2 * q + 1] = pack2(bv.z + dv.z + ev.z, bv.w + dv.w + ev.w);
        }
    }

    // matvec: acc += e_row @ Wc   (LDCU.64 weights + FFMA2)
    const ull* W2 = (const ull*)cWc;
    #pragma unroll 4
    for (int k = 0; k < 64; k++) {
        const float ek = sE[k][tid];
        const ull e2 = pack2(ek, ek);
        const ull* w = W2 + k * 32;
        #pragma unroll
        for (int j = 0; j < 32; j++) acc[j] = fma2(e2, w[j], acc[j]);
    }

    // epilogue: z store, sigmoid gate, num/den atomics; repack z into acc for stats
    const float zn = enorm[edge];
    const float4* B4 = ((const float4*)g_Bh) + (size_t)s * 16;
    float4* num4 = ((float4*)g_num) + (size_t)d * 16;
    float4* den4 = ((float4*)g_den) + (size_t)d * 16;
    float4* z4 = ((float4*)g_z) + (size_t)edge * 16;

    #pragma unroll
    for (int q = 0; q < 16; q++) {
        const float2 a0 = unpack2(acc[2 * q]);
        const float2 a1 = unpack2(acc[2 * q + 1]);
        float4 sg;
        sg.x = sigmoidf_fast(a0.x); sg.y = sigmoidf_fast(a0.y);
        sg.z = sigmoidf_fast(a1.x); sg.w = sigmoidf_fast(a1.y);
        const float4 zq = make_float4(a0.x * zn, a0.y * zn, a1.x * zn, a1.y * zn);
        if (MODE <= 1) {
            z4[q] = zq;
            acc[2 * q]     = pack2(zq.x, zq.y);
            acc[2 * q + 1] = pack2(zq.z, zq.w);
        }
        const float4 bq = B4[q];
        atomicAdd(&num4[q], make_float4(sg.x * bq.x, sg.y * bq.y, sg.z * bq.z, sg.w * bq.w));
        atomicAdd(&den4[q], sg);
    }

    // fused BN stats over z: block reduction in shared, striped double atomics
    if (MODE <= 1) {
        __syncthreads();
        #pragma unroll
        for (int q = 0; q < 16; q++) {
            const float2 a0 = unpack2(acc[2 * q]);
            const float2 a1 = unpack2(acc[2 * q + 1]);
            sE[4 * q + 0][tid] = a0.x; sE[4 * q + 1][tid] = a0.y;
            sE[4 * q + 2][tid] = a1.x; sE[4 * q + 3][tid] = a1.y;
        }
        __syncthreads();
        const int c = tid & 63, part = tid >> 6;
        float sacc = 0.f;
        if (part == 0) {
            #pragma unroll 8
            for (int e = 0; e < 128; e++) sacc += sE[c][e];
        } else {
            #pragma unroll 8
            for (int e = 0; e < 128; e++) { const float v = sE[c][e]; sacc = fmaf(v, v, sacc); }
        }
        atomicAdd(&g_statsP[blockIdx.x & 31][part * 64 + c], (double)sacc);
    }
}

// ---------- node aggregate + graph norm + BN stats over hn ----------
__global__ void __launch_bounds__(256) k_node_B(const float* __restrict__ nnorm) {
    const int c = threadIdx.x & 63;
    const int slot = threadIdx.x >> 6;
    double s = 0.0, q = 0.0;
    for (int n = blockIdx.x * 4 + slot; n < Nn; n += gridDim.x * 4) {
        const size_t idx = (size_t)n * 64 + c;
        const float v = (g_Ah[idx] + g_num[idx] / (g_den[idx] + 1e-6f)) * nnorm[n];
        g_hn[idx] = v;
        s += v;
        q += (double)v * (double)v;
    }
    __shared__ double sh[512];
    sh[threadIdx.x] = s;
    sh[256 + threadIdx.x] = q;
    __syncthreads();
    if (threadIdx.x < 64) {
        s = sh[c] + sh[c + 64] + sh[c + 128] + sh[c + 192];
        q = sh[256 + c] + sh[256 + c + 64] + sh[256 + c + 128] + sh[256 + c + 192];
        const int st = blockIdx.x & 31;
        atomicAdd(&g_statsP[st][128 + c], s);
        atomicAdd(&g_statsP[st][192 + c], q);
    }
}

__global__ void k_finalize() {
    const int c = threadIdx.x;  // 64 threads
    double se = 0.0, qe = 0.0, sh2 = 0.0, qh = 0.0;
    #pragma unroll 4
    for (int st = 0; st < 32; st++) {
        se  += g_statsP[st][c];
        qe  += g_statsP[st][64 + c];
        sh2 += g_statsP[st][128 + c];
        qh  += g_statsP[st][192 + c];
    }
    const double mu_e = se / (double)Ee;
    const double var_e = qe / (double)Ee - mu_e * mu_e;
    g_bnp[c] = (float)mu_e;
    g_bnp[64 + c] = (float)(1.0 / sqrt(var_e + 1e-5));
    const double mu_h = sh2 / (double)Nn;
    const double var_h = qh / (double)Nn - mu_h * mu_h;
    g_bnp[128 + c] = (float)mu_h;
    g_bnp[192 + c] = (float)(1.0 / sqrt(var_h + 1e-5));
}

// ---------- readout: fused last-layer node BN+residual + per-graph mean ----------
__global__ void k_zero_out(float* __restrict__ out) {
    const int i = blockIdx.x * 256 + threadIdx.x;
    if (i < Gg * 64) out[i] = 0.f;
    if (i < Gg) g_cnt[i] = 0.f;
}

__global__ void __launch_bounds__(256) k_readout(const int* __restrict__ gid,
                                                 const float* __restrict__ gamH,
                                                 const float* __restrict__ betH,
                                                 float* __restrict__ out) {
    const int i = blockIdx.x * 256 + threadIdx.x;   // exact: 3125*256 = Nn*16
    const int q = i & 15, n = i >> 4;
    float4 hv = ((const float4*)g_h)[i];
    const float4 hn = ((const float4*)g_hn)[i];
    const float4 g4 = ((const float4*)gamH)[q];
    const float4 b4 = ((const float4*)betH)[q];
    const float4 mu = ((const float4*)(g_bnp + 128))[q];
    const float4 iv = ((const float4*)(g_bnp + 192))[q];
    hv.x += fmaxf(0.f, g4.x * (hn.x - mu.x) * iv.x + b4.x);
    hv.y += fmaxf(0.f, g4.y * (hn.y - mu.y) * iv.y + b4.y);
    hv.z += fmaxf(0.f, g4.z * (hn.z - mu.z) * iv.z + b4.z);
    hv.w += fmaxf(0.f, g4.w * (hn.w - mu.w) * iv.w + b4.w);
    const int g = gid[n];
    atomicAdd(((float4*)out) + (size_t)g * 16 + q, hv);
    if (q == 0) atomicAdd(&g_cnt[g], 1.0f);
}

__global__ void k_div(float* __restrict__ out) {
    const int i = blockIdx.x * 256 + threadIdx.x;   // exact 32768
    out[i] /= fmaxf(g_cnt[i >> 6], 1.0f);
}

// =====================================================================
extern "C" void kernel_launch(void* const* d_in, const int* in_sizes, int n_in,
                              void* d_out, int out_size) {
    const float* nodes_feat = (const float*)d_in[0];
    const float* edges_feat = (const float*)d_in[1];
    const float* nnorm      = (const float*)d_in[2];
    const float* enorm      = (const float*)d_in[3];
    const float* W_h        = (const float*)d_in[4];
    const float* b_h        = (const float*)d_in[5];
    const float* W_e        = (const float*)d_in[6];
    const float* b_e        = (const float*)d_in[7];
    const float* Wa         = (const float*)d_in[8];
    const float* ba         = (const float*)d_in[9];
    const float* Wb         = (const float*)d_in[10];
    const float* bb         = (const float*)d_in[11];
    const float* Wc         = (const float*)d_in[12];
    const float* bc         = (const float*)d_in[13];
    const float* Wd         = (const float*)d_in[14];
    const float* bd         = (const float*)d_in[15];
    const float* We         = (const float*)d_in[16];
    const float* be         = (const float*)d_in[17];
    const float* gamma_h    = (const float*)d_in[18];
    const float* beta_h     = (const float*)d_in[19];
    const float* gamma_e    = (const float*)d_in[20];
    const float* beta_e     = (const float*)d_in[21];
    const int*   esrc       = (const int*)d_in[22];
    const int*   edst       = (const int*)d_in[23];
    const int*   gid        = (const int*)d_in[24];
    float* out = (float*)d_out;

    const int dynSmem = 4 * 4096 * 4 + 16 * 64 * 4;
    cudaFuncSetAttribute(k_node_gemm<0>, cudaFuncAttributeMaxDynamicSharedMemorySize, dynSmem);
    cudaFuncSetAttribute(k_node_gemm<1>, cudaFuncAttributeMaxDynamicSharedMemorySize, dynSmem);

    k_embed_h<<<(Nn + 63) / 64, 256>>>(nodes_feat, W_h, b_h);

    for (int l = 0; l < 4; l++) {
        cudaMemcpyToSymbolAsync(cWc, Wc + (size_t)l * 4096, 4096 * sizeof(float), 0,
                                cudaMemcpyDeviceToDevice, 0);
        if (l == 0)
            k_node_gemm<0><<<(Nn + 63) / 64, 256, dynSmem>>>(
                Wa, Wb, Wd, We, ba, bb, bd, be, gamma_h, beta_h);
        else
            k_node_gemm<1><<<(Nn + 63) / 64, 256, dynSmem>>>(
                Wa + (size_t)l * 4096, Wb + (size_t)l * 4096,
                Wd + (size_t)l * 4096, We + (size_t)l * 4096,
                ba + l * 64, bb + l * 64, bd + l * 64, be + l * 64,
                gamma_h + (l - 1) * 64, beta_h + (l - 1) * 64);

        const float* gE = gamma_e + (l > 0 ? (l - 1) * 64 : 0);
        const float* bE = beta_e  + (l > 0 ? (l - 1) * 64 : 0);
        if (l == 0)
            k_edge_A<0><<<Ee / 128, 128>>>(bc, esrc, edst, enorm, edges_feat, W_e, b_e, gE, bE);
        else if (l < 3)
            k_edge_A<1><<<Ee / 128, 128>>>(bc + l * 64, esrc, edst, enorm,
                                           edges_feat, W_e, b_e, gE, bE);
        else
            k_edge_A<2><<<Ee / 128, 128>>>(bc + l * 64, esrc, edst, enorm,
                                           edges_feat, W_e, b_e, gE, bE);

        k_node_B<<<128, 256>>>(nnorm);
        k_finalize<<<1, 64>>>();
    }

    k_zero_out<<<128, 256>>>(out);
    k_readout<<<Nn * 16 / 256, 256>>>(gid, gamma_h + 3 * 64, beta_h + 3 * 64, out);
    k_div<<<Gg * 64 / 256, 256>>>(out);
}

// round 3
// speedup vs baseline: 1.5457x; 1.5457x over previous
#include <cuda_runtime.h>

// Problem constants (fixed by the dataset)
#define Nn   50000
#define Ee   800000
#define Gg   512
#define DINc 128

typedef unsigned long long ull;

// ---------- f32x2 packed-FMA helpers (sm_103a) ----------
__device__ __forceinline__ ull fma2(ull a, ull b, ull c) {
    ull d;
    asm("fma.rn.f32x2 %0, %1, %2, %3;" : "=l"(d) : "l"(a), "l"(b), "l"(c));
    return d;
}
__device__ __forceinline__ ull pack2(float x, float y) {
    ull r;
    asm("mov.b64 %0, {%1,%2};" : "=l"(r) : "f"(x), "f"(y));
    return r;
}
__device__ __forceinline__ float2 unpack2(ull v) {
    float2 r;
    asm("mov.b64 {%0,%1}, %2;" : "=f"(r.x), "=f"(r.y) : "l"(v));
    return r;
}
__device__ __forceinline__ float sigmoidf_fast(float x) {
    return __fdividef(1.0f, 1.0f + __expf(-x));
}

// Per-layer edge weight matrix in constant memory -> warp-uniform LDCU.64 reads.
__constant__ float cWc[64 * 64];

// ---------- scratch (static device globals) ----------
__device__ float  g_h [(size_t)Nn * 64];
__device__ float  g_e [(size_t)Ee * 64];
__device__ float  g_z [(size_t)Ee * 64];
__device__ float  g_Ah[(size_t)Nn * 64];
__device__ float  g_Bh[(size_t)Nn * 64];
__device__ float  g_Dh[(size_t)Nn * 64];
__device__ float  g_Eh[(size_t)Nn * 64];
__device__ float  g_num[(size_t)Nn * 64];
__device__ float  g_den[(size_t)Nn * 64];
__device__ float  g_hn[(size_t)Nn * 64];
__device__ double g_statsP[32][256];   // striped: [0:64) e_sum [64:128) e_sq [128:192) h_sum [192:256) h_sq
__device__ float  g_bnp[256];          // [0:64) mu_e [64:128) inv_e [128:192) mu_h [192:256) inv_h
__device__ float  g_cnt[Gg];

// ---------- initial node embedding: h = nodes_feat @ W_h + b_h ----------
__global__ void __launch_bounds__(256) k_embed_h(const float* __restrict__ x,
                                                 const float* __restrict__ W,
                                                 const float* __restrict__ b) {
    __shared__ __align__(16) float sW[DINc][64];
    __shared__ __align__(16) float sx[16][DINc];
    const int t = threadIdx.x;
    for (int i = t; i < DINc * 64 / 4; i += 256)
        ((float4*)&sW[0][0])[i] = ((const float4*)W)[i];

    const int cq = t & 15, m = t >> 4;
    const float4 bias = ((const float4*)b)[cq];
    const int base = blockIdx.x * 64;

    for (int it = 0; it < 4; it++) {
        const int n0 = base + it * 16;
        __syncthreads();
        for (int i = t; i < 16 * DINc / 4; i += 256) {
            const int row = i >> 5, c4 = i & 31;
            const int n = n0 + row;
            float4 v = make_float4(0.f, 0.f, 0.f, 0.f);
            if (n < Nn) v = ((const float4*)x)[(size_t)n * 32 + c4];
            ((float4*)&sx[row][0])[c4] = v;
        }
        __syncthreads();
        float4 acc = bias;
        #pragma unroll 8
        for (int k = 0; k < DINc; k++) {
            const float xv = sx[m][k];
            const float4 w = ((const float4*)&sW[k][0])[cq];
            acc.x += xv * w.x; acc.y += xv * w.y;
            acc.z += xv * w.z; acc.w += xv * w.w;
        }
        const int n = n0 + m;
        if (n < Nn) ((float4*)g_h)[(size_t)n * 16 + cq] = acc;
    }
}

// ---------- initial edge embedding ----------
__global__ void __launch_bounds__(256) k_embed_e(const float* __restrict__ ef,
                                                 const float* __restrict__ We_,
                                                 const float* __restrict__ be_) {
    const size_t i = (size_t)blockIdx.x * 256 + threadIdx.x;  // quad index
    if (i >= (size_t)Ee * 16) return;
    const int q = (int)(i & 15);
    const size_t ed = i >> 4;
    const float f = ef[ed];
    const float4 w = ((const float4*)We_)[q];
    const float4 b = ((const float4*)be_)[q];
    ((float4*)g_e)[i] = make_float4(fmaf(f, w.x, b.x), fmaf(f, w.y, b.y),
                                    fmaf(f, w.z, b.z), fmaf(f, w.w, b.w));
}

// ---------- per-layer node GEMMs (Ah,Bh,Dh,Eh) + num/den zero + stats zero ----------
extern __shared__ float dsm[];
__global__ void __launch_bounds__(256) k_node_gemm(
        const float* __restrict__ Wa, const float* __restrict__ Wb,
        const float* __restrict__ Wd, const float* __restrict__ We_,
        const float* __restrict__ ba_, const float* __restrict__ bb_,
        const float* __restrict__ bd_, const float* __restrict__ be_) {
    float* sW = dsm;              // 4 * 4096 floats
    float* sx = dsm + 4 * 4096;   // 16 * 64 floats
    const int t = threadIdx.x;

    if (blockIdx.x == 0) {        // zero striped BN stats for this layer
        double* p = &g_statsP[0][0];
        for (int i = t; i < 32 * 256; i += 256) p[i] = 0.0;
    }

    for (int i = t; i < 1024; i += 256) ((float4*)(sW + 0 * 4096))[i] = ((const float4*)Wa)[i];
    for (int i = t; i < 1024; i += 256) ((float4*)(sW + 1 * 4096))[i] = ((const float4*)Wb)[i];
    for (int i = t; i < 1024; i += 256) ((float4*)(sW + 2 * 4096))[i] = ((const float4*)Wd)[i];
    for (int i = t; i < 1024; i += 256) ((float4*)(sW + 3 * 4096))[i] = ((const float4*)We_)[i];

    const int cq = t & 15, m = t >> 4;
    const float4 bA = ((const float4*)ba_)[cq];
    const float4 bB = ((const float4*)bb_)[cq];
    const float4 bD = ((const float4*)bd_)[cq];
    const float4 bE = ((const float4*)be_)[cq];
    const int base = blockIdx.x * 64;

    for (int it = 0; it < 4; it++) {
        const int n0 = base + it * 16;
        __syncthreads();
        {
            const int row = t >> 4, c4 = t & 15;
            const int n = n0 + row;
            float4 v = make_float4(0.f, 0.f, 0.f, 0.f);
            if (n < Nn) v = ((const float4*)g_h)[(size_t)n * 16 + c4];
            ((float4*)sx)[row * 16 + c4] = v;
        }
        __syncthreads();
        float4 aA = bA, aB = bB, aD = bD, aE = bE;
        #pragma unroll 4
        for (int k = 0; k < 64; k++) {
            const float xv = sx[m * 64 + k];
            const float4 wA = ((const float4*)(sW + 0 * 4096 + k * 64))[cq];
            const float4 wB = ((const float4*)(sW + 1 * 4096 + k * 64))[cq];
            const float4 wD = ((const float4*)(sW + 2 * 4096 + k * 64))[cq];
            const float4 wE = ((const float4*)(sW + 3 * 4096 + k * 64))[cq];
            aA.x += xv * wA.x; aA.y += xv * wA.y; aA.z += xv * wA.z; aA.w += xv * wA.w;
            aB.x += xv * wB.x; aB.y += xv * wB.y; aB.z += xv * wB.z; aB.w += xv * wB.w;
            aD.x += xv * wD.x; aD.y += xv * wD.y; aD.z += xv * wD.z; aD.w += xv * wD.w;
            aE.x += xv * wE.x; aE.y += xv * wE.y; aE.z += xv * wE.z; aE.w += xv * wE.w;
        }
        const int n = n0 + m;
        if (n < Nn) {
            const size_t o = (size_t)n * 16 + cq;
            ((float4*)g_Ah)[o] = aA;
            ((float4*)g_Bh)[o] = aB;
            ((float4*)g_Dh)[o] = aD;
            ((float4*)g_Eh)[o] = aE;
            ((float4*)g_num)[o] = make_float4(0.f, 0.f, 0.f, 0.f);
            ((float4*)g_den)[o] = make_float4(0.f, 0.f, 0.f, 0.f);
        }
    }
}

// ---------- fused edge pass A (round-1 register form) ----------
// WZ=1: write z (layers 0..2).  WZ=0: last layer, no z store.
template<int WZ>
__global__ void __launch_bounds__(256) k_edge_A(const float* __restrict__ bc_,
                                                const int* __restrict__ src,
                                                const int* __restrict__ dst,
                                                const float* __restrict__ enorm) {
    const int t = blockIdx.x * 256 + threadIdx.x;
    if (t >= Ee) return;
    const int s = src[t], d = dst[t];

    const float4* e4 = ((const float4*)g_e) + (size_t)t * 16;
    const float4* D4 = ((const float4*)g_Dh) + (size_t)s * 16;
    const float4* E4 = ((const float4*)g_Eh) + (size_t)d * 16;
    const float4* b4 = (const float4*)bc_;

    ull acc[32];
    #pragma unroll
    for (int q = 0; q < 16; q++) {
        const float4 bv = b4[q], dv = D4[q], ev = E4[q];
        acc[2 * q]     = pack2(bv.x + dv.x + ev.x, bv.y + dv.y + ev.y);
        acc[2 * q + 1] = pack2(bv.z + dv.z + ev.z, bv.w + dv.w + ev.w);
    }

    const ull* W2 = (const ull*)cWc;   // row k, channel pair j -> W2[k*32 + j]
    #pragma unroll 2
    for (int q = 0; q < 16; q++) {
        const float4 ev = e4[q];
        #pragma unroll
        for (int kk = 0; kk < 4; kk++) {
            const float ek = (kk == 0) ? ev.x : (kk == 1) ? ev.y : (kk == 2) ? ev.z : ev.w;
            const ull e2 = pack2(ek, ek);
            const ull* w = W2 + (q * 4 + kk) * 32;
            #pragma unroll
            for (int j = 0; j < 32; j++) acc[j] = fma2(e2, w[j], acc[j]);
        }
    }

    const float zn = enorm[t];
    float4* z4 = ((float4*)g_z) + (size_t)t * 16;
    const float4* B4 = ((const float4*)g_Bh) + (size_t)s * 16;
    float4* num4 = ((float4*)g_num) + (size_t)d * 16;
    float4* den4 = ((float4*)g_den) + (size_t)d * 16;

    #pragma unroll
    for (int q = 0; q < 16; q++) {
        const float2 a0 = unpack2(acc[2 * q]);
        const float2 a1 = unpack2(acc[2 * q + 1]);
        float4 sg;
        sg.x = sigmoidf_fast(a0.x); sg.y = sigmoidf_fast(a0.y);
        sg.z = sigmoidf_fast(a1.x); sg.w = sigmoidf_fast(a1.y);
        if (WZ) z4[q] = make_float4(a0.x * zn, a0.y * zn, a1.x * zn, a1.y * zn);
        const float4 bq = B4[q];
        atomicAdd(&num4[q], make_float4(sg.x * bq.x, sg.y * bq.y, sg.z * bq.z, sg.w * bq.w));
        atomicAdd(&den4[q], sg);
    }
}

// ---------- BN stats over z (wide grid, striped double atomics) ----------
__global__ void __launch_bounds__(256) k_estats() {
    const int c = threadIdx.x & 63;
    const int slot = threadIdx.x >> 6;
    double s = 0.0, q = 0.0;
    for (size_t i = (size_t)blockIdx.x * 4 + slot; i < Ee; i += (size_t)gridDim.x * 4) {
        const float v = g_z[i * 64 + c];
        s += v;
        q += (double)v * (double)v;
    }
    __shared__ double sh[512];
    sh[threadIdx.x] = s;
    sh[256 + threadIdx.x] = q;
    __syncthreads();
    if (threadIdx.x < 64) {
        s = sh[c] + sh[c + 64] + sh[c + 128] + sh[c + 192];
        q = sh[256 + c] + sh[256 + c + 64] + sh[256 + c + 128] + sh[256 + c + 192];
        const int st = blockIdx.x & 31;
        atomicAdd(&g_statsP[st][c], s);
        atomicAdd(&g_statsP[st][64 + c], q);
    }
}

// ---------- node aggregate + graph norm + BN stats over hn ----------
__global__ void __launch_bounds__(256) k_node_B(const float* __restrict__ nnorm) {
    const int c = threadIdx.x & 63;
    const int slot = threadIdx.x >> 6;
    double s = 0.0, q = 0.0;
    for (int n = blockIdx.x * 4 + slot; n < Nn; n += gridDim.x * 4) {
        const size_t idx = (size_t)n * 64 + c;
        const float v = (g_Ah[idx] + g_num[idx] / (g_den[idx] + 1e-6f)) * nnorm[n];
        g_hn[idx] = v;
        s += v;
        q += (double)v * (double)v;
    }
    __shared__ double sh[512];
    sh[threadIdx.x] = s;
    sh[256 + threadIdx.x] = q;
    __syncthreads();
    if (threadIdx.x < 64) {
        s = sh[c] + sh[c + 64] + sh[c + 128] + sh[c + 192];
        q = sh[256 + c] + sh[256 + c + 64] + sh[256 + c + 128] + sh[256 + c + 192];
        const int st = blockIdx.x & 31;
        atomicAdd(&g_statsP[st][128 + c], s);
        atomicAdd(&g_statsP[st][192 + c], q);
    }
}

__global__ void k_finalize() {
    const int c = threadIdx.x;  // 64 threads
    double se = 0.0, qe = 0.0, sh2 = 0.0, qh = 0.0;
    #pragma unroll 4
    for (int st = 0; st < 32; st++) {
        se  += g_statsP[st][c];
        qe  += g_statsP[st][64 + c];
        sh2 += g_statsP[st][128 + c];
        qh  += g_statsP[st][192 + c];
    }
    const double mu_e = se / (double)Ee;
    const double var_e = qe / (double)Ee - mu_e * mu_e;
    g_bnp[c] = (float)mu_e;
    g_bnp[64 + c] = (float)(1.0 / sqrt(var_e + 1e-5));
    const double mu_h = sh2 / (double)Nn;
    const double var_h = qh / (double)Nn - mu_h * mu_h;
    g_bnp[128 + c] = (float)mu_h;
    g_bnp[192 + c] = (float)(1.0 / sqrt(var_h + 1e-5));
}

// ---------- node residual update: h += relu(BN(hn)) ----------
__global__ void __launch_bounds__(256) k_node_C(const float* __restrict__ gam,
                                                const float* __restrict__ bet) {
    const int i = blockIdx.x * 256 + threadIdx.x;
    if (i >= Nn * 16) return;
    const int q = i & 15;
    float4 hv = ((float4*)g_h)[i];
    const float4 hn = ((float4*)g_hn)[i];
    const float4 g4 = ((const float4*)gam)[q];
    const float4 b4 = ((const float4*)bet)[q];
    const float4 mu = ((const float4*)(g_bnp + 128))[q];
    const float4 iv = ((const float4*)(g_bnp + 192))[q];
    hv.x += fmaxf(0.f, g4.x * (hn.x - mu.x) * iv.x + b4.x);
    hv.y += fmaxf(0.f, g4.y * (hn.y - mu.y) * iv.y + b4.y);
    hv.z += fmaxf(0.f, g4.z * (hn.z - mu.z) * iv.z + b4.z);
    hv.w += fmaxf(0.f, g4.w * (hn.w - mu.w) * iv.w + b4.w);
    ((float4*)g_h)[i] = hv;
}

// ---------- edge residual update: e += relu(BN(z)) ----------
__global__ void __launch_bounds__(256) k_edge_C(const float* __restrict__ gam,
                                                const float* __restrict__ bet) {
    const size_t i = (size_t)blockIdx.x * 256 + threadIdx.x;
    if (i >= (size_t)Ee * 16) return;
    const int q = (int)(i & 15);
    float4 evv = ((float4*)g_e)[i];
    const float4 zv = ((float4*)g_z)[i];
    const float4 g4 = ((const float4*)gam)[q];
    const float4 b4 = ((const float4*)bet)[q];
    const float4 mu = ((const float4*)(g_bnp + 0))[q];
    const float4 iv = ((const float4*)(g_bnp + 64))[q];
    evv.x += fmaxf(0.f, g4.x * (zv.x - mu.x) * iv.x + b4.x);
    evv.y += fmaxf(0.f, g4.y * (zv.y - mu.y) * iv.y + b4.y);
    evv.z += fmaxf(0.f, g4.z * (zv.z - mu.z) * iv.z + b4.z);
    evv.w += fmaxf(0.f, g4.w * (zv.w - mu.w) * iv.w + b4.w);
    ((float4*)g_e)[i] = evv;
}

// ---------- readout: fused last-layer node BN+residual + per-graph mean ----------
__global__ void k_zero_out(float* __restrict__ out) {
    const int i = blockIdx.x * 256 + threadIdx.x;
    if (i < Gg * 64) out[i] = 0.f;
    if (i < Gg) g_cnt[i] = 0.f;
}

__global__ void __launch_bounds__(256) k_readout(const int* __restrict__ gid,
                                                 const float* __restrict__ gamH,
                                                 const float* __restrict__ betH,
                                                 float* __restrict__ out) {
    const int i = blockIdx.x * 256 + threadIdx.x;   // exact: Nn*16 = 800000
    const int q = i & 15, n = i >> 4;
    float4 hv = ((const float4*)g_h)[i];
    const float4 hn = ((const float4*)g_hn)[i];
    const float4 g4 = ((const float4*)gamH)[q];
    const float4 b4 = ((const float4*)betH)[q];
    const float4 mu = ((const float4*)(g_bnp + 128))[q];
    const float4 iv = ((const float4*)(g_bnp + 192))[q];
    hv.x += fmaxf(0.f, g4.x * (hn.x - mu.x) * iv.x + b4.x);
    hv.y += fmaxf(0.f, g4.y * (hn.y - mu.y) * iv.y + b4.y);
    hv.z += fmaxf(0.f, g4.z * (hn.z - mu.z) * iv.z + b4.z);
    hv.w += fmaxf(0.f, g4.w * (hn.w - mu.w) * iv.w + b4.w);
    const int g = gid[n];
    atomicAdd(((float4*)out) + (size_t)g * 16 + q, hv);
    if (q == 0) atomicAdd(&g_cnt[g], 1.0f);
}

__global__ void k_div(float* __restrict__ out) {
    const int i = blockIdx.x * 256 + threadIdx.x;   // exact 32768
    out[i] /= fmaxf(g_cnt[i >> 6], 1.0f);
}

// =====================================================================
extern "C" void kernel_launch(void* const* d_in, const int* in_sizes, int n_in,
                              void* d_out, int out_size) {
    const float* nodes_feat = (const float*)d_in[0];
    const float* edges_feat = (const float*)d_in[1];
    const float* nnorm      = (const float*)d_in[2];
    const float* enorm      = (const float*)d_in[3];
    const float* W_h        = (const float*)d_in[4];
    const float* b_h        = (const float*)d_in[5];
    const float* W_e        = (const float*)d_in[6];
    const float* b_e        = (const float*)d_in[7];
    const float* Wa         = (const float*)d_in[8];
    const float* ba         = (const float*)d_in[9];
    const float* Wb         = (const float*)d_in[10];
    const float* bb         = (const float*)d_in[11];
    const float* Wc         = (const float*)d_in[12];
    const float* bc         = (const float*)d_in[13];
    const float* Wd         = (const float*)d_in[14];
    const float* bd         = (const float*)d_in[15];
    const float* We         = (const float*)d_in[16];
    const float* be         = (const float*)d_in[17];
    const float* gamma_h    = (const float*)d_in[18];
    const float* beta_h     = (const float*)d_in[19];
    const float* gamma_e    = (const float*)d_in[20];
    const float* beta_e     = (const float*)d_in[21];
    const int*   esrc       = (const int*)d_in[22];
    const int*   edst       = (const int*)d_in[23];
    const int*   gid        = (const int*)d_in[24];
    float* out = (float*)d_out;

    const int dynSmem = 4 * 4096 * 4 + 16 * 64 * 4;
    cudaFuncSetAttribute(k_node_gemm, cudaFuncAttributeMaxDynamicSharedMemorySize, dynSmem);

    // Launch order puts layer-0 k_edge_A at profiled slot #5
    k_embed_h<<<(Nn + 63) / 64, 256>>>(nodes_feat, W_h, b_h);                       // 1
    k_embed_e<<<(int)(((size_t)Ee * 16 + 255) / 256), 256>>>(edges_feat, W_e, b_e); // 2

    for (int l = 0; l < 4; l++) {
        cudaMemcpyToSymbolAsync(cWc, Wc + (size_t)l * 4096, 4096 * sizeof(float), 0,
                                cudaMemcpyDeviceToDevice, 0);                        // 3 (l=0)
        k_node_gemm<<<(Nn + 63) / 64, 256, dynSmem>>>(
            Wa + (size_t)l * 4096, Wb + (size_t)l * 4096,
            Wd + (size_t)l * 4096, We + (size_t)l * 4096,
            ba + l * 64, bb + l * 64, bd + l * 64, be + l * 64);                     // 4 (l=0)

        if (l < 3) {
            k_edge_A<1><<<Ee / 256, 256>>>(bc + l * 64, esrc, edst, enorm);          // 5 (l=0) <- profiled
            k_estats<<<1024, 256>>>();
        } else {
            k_edge_A<0><<<Ee / 256, 256>>>(bc + l * 64, esrc, edst, enorm);
        }

        k_node_B<<<1024, 256>>>(nnorm);
        k_finalize<<<1, 64>>>();

        if (l < 3) {
            k_node_C<<<(Nn * 16 + 255) / 256, 256>>>(gamma_h + l * 64, beta_h + l * 64);
            k_edge_C<<<(int)(((size_t)Ee * 16 + 255) / 256), 256>>>(gamma_e + l * 64,
                                                                    beta_e + l * 64);
        }
    }

    k_zero_out<<<128, 256>>>(out);
    k_readout<<<Nn * 16 / 256, 256>>>(gid, gamma_h + 3 * 64, beta_h + 3 * 64, out);
    k_div<<<Gg * 64 / 256, 256>>>(out);
}